// round 1
// baseline (speedup 1.0000x reference)
#include <cuda_runtime.h>

#define HH 64
#define WW 64
#define NPIX 4096
#define NB 4
#define C1 32
#define C2 64
#define C3 256

// ---------------- static device scratch (no allocations allowed) ----------------
__device__ float g_T1[NB * C1 * NPIX];     // conv1 out (reused for x1 then x2)
__device__ float g_T2[NB * C2 * NPIX];     // conv2 out
__device__ float g_F2[NB * C3 * NPIX];     // features of x2
__device__ float g_B2N[NB * NPIX];         // ||f2||^2 per key
__device__ int   g_IDX[NB * NPIX];         // argmin indices
__device__ float g_Wt2[288 * C2];          // w2 transposed to [k][co]
__device__ float g_Wt3[576 * C3];          // w3 transposed to [k][co]

// ---------------- weight transpose: w[co][k] -> wT[k][co] ----------------
__global__ void transpose_w_kernel(const float* __restrict__ w, float* __restrict__ wT,
                                   int CO, int K) {
    int t = blockIdx.x * blockDim.x + threadIdx.x;
    if (t < CO * K) {
        int co = t / K;
        int k = t - co * K;
        wT[k * CO + co] = w[t];
    }
}

// ---------------- conv1: 1 -> 32 channels, tiny direct conv ----------------
__global__ void conv1_kernel(const float* __restrict__ x, const float* __restrict__ w,
                             const float* __restrict__ bias, float* __restrict__ out) {
    int p = blockIdx.x * blockDim.x + threadIdx.x;
    int b = blockIdx.y;
    if (p >= NPIX) return;
    int y = p >> 6, xx = p & 63;
    const float* xb = x + (long)b * NPIX;
    float in[9];
#pragma unroll
    for (int ky = 0; ky < 3; ky++)
#pragma unroll
        for (int kx = 0; kx < 3; kx++) {
            int yy = y + ky - 1, xc = xx + kx - 1;
            in[ky * 3 + kx] =
                ((unsigned)yy < (unsigned)HH && (unsigned)xc < (unsigned)WW) ? xb[yy * WW + xc] : 0.f;
        }
#pragma unroll 4
    for (int co = 0; co < C1; co++) {
        float acc = bias[co];
#pragma unroll
        for (int t = 0; t < 9; t++) acc += w[co * 9 + t] * in[t];
        out[((long)b * C1 + co) * NPIX + p] = acc;
    }
}

// ---------------- implicit-GEMM conv: out[co][n] = sum_k wT[k][co] * patch[k][n] ----------------
// BN=128, TN=8, BK=8 fixed; BM/TM templated (conv2: 64/4, conv3: 128/8). 256 threads.
template <int BM, int TM>
__global__ void conv_gemm_kernel(const float* __restrict__ in, int CI,
                                 const float* __restrict__ wT, int Ktot, int CO,
                                 const float* __restrict__ bias,
                                 float* __restrict__ out, long outBatchStride) {
    const int BN = 128, TN = 8, BK = 8;
    __shared__ __align__(16) float As[BK][BM];
    __shared__ __align__(16) float Bs[BK][BN];
    int bb = blockIdx.z;
    int m0 = blockIdx.y * BM;
    int n0 = blockIdx.x * BN;
    int tid = threadIdx.x;
    int tx = tid & 15;
    int ty = tid >> 4;
    long inBase = (long)bb * CI * NPIX;

    float acc[TM][TN];
#pragma unroll
    for (int u = 0; u < TM; u++)
#pragma unroll
        for (int v = 0; v < TN; v++) acc[u][v] = 0.f;

    for (int k0 = 0; k0 < Ktot; k0 += BK) {
        // A tile: weights (coalesced, conflict-free)
#pragma unroll
        for (int t = tid; t < BM * BK; t += 256) {
            int m = t % BM;
            int k = t / BM;
            As[k][m] = wT[(long)(k0 + k) * CO + m0 + m];
        }
        // B tile: implicit im2col patches
#pragma unroll
        for (int t = tid; t < BN * BK; t += 256) {
            int n = t % BN;
            int k = t / BN;
            int gk = k0 + k;
            int ci = gk / 9;
            int tap = gk - ci * 9;
            int ky = tap / 3 - 1;
            int kx = tap - (tap / 3) * 3 - 1;
            int gp = n0 + n;
            int y = (gp >> 6) + ky;
            int x = (gp & 63) + kx;
            float v = 0.f;
            if ((unsigned)y < (unsigned)HH && (unsigned)x < (unsigned)WW)
                v = in[inBase + (long)ci * NPIX + (y << 6) + x];
            Bs[k][n] = v;
        }
        __syncthreads();
#pragma unroll
        for (int kk = 0; kk < BK; kk++) {
            float a[TM], bv[TN];
#pragma unroll
            for (int u = 0; u < TM; u += 4)
                *(float4*)&a[u] = *(const float4*)&As[kk][ty * TM + u];
#pragma unroll
            for (int v = 0; v < TN; v += 4)
                *(float4*)&bv[v] = *(const float4*)&Bs[kk][tx * TN + v];
#pragma unroll
            for (int u = 0; u < TM; u++)
#pragma unroll
                for (int v = 0; v < TN; v++) acc[u][v] += a[u] * bv[v];
        }
        __syncthreads();
    }
#pragma unroll
    for (int u = 0; u < TM; u++) {
        int m = m0 + ty * TM + u;
        float bval = bias[m];
        long base = (long)bb * outBatchStride + (long)m * NPIX + n0 + tx * TN;
#pragma unroll
        for (int v = 0; v < TN; v += 4) {
            float4 o;
            o.x = acc[u][v + 0] + bval;
            o.y = acc[u][v + 1] + bval;
            o.z = acc[u][v + 2] + bval;
            o.w = acc[u][v + 3] + bval;
            *(float4*)&out[base + v] = o;
        }
    }
}

// ---------------- key row norms: b2n[b][j] = sum_c f2[b][c][j]^2 ----------------
__global__ void rownorm_kernel(const float* __restrict__ f2, float* __restrict__ b2n) {
    int j = blockIdx.x * blockDim.x + threadIdx.x;
    int b = blockIdx.y;
    if (j >= NPIX) return;
    const float* p = f2 + (long)b * C3 * NPIX + j;
    float s = 0.f;
#pragma unroll 8
    for (int c = 0; c < C3; c++) {
        float v = p[(long)c * NPIX];
        s += v * v;
    }
    b2n[(long)b * NPIX + j] = s;
}

// ---------------- fused distance GEMM + argmin ----------------
// dist(i,j) = b2n[j] - 2 * sum_c Q[c][i] * K[c][j]  (a2 term constant per row)
// Q read from d_out (f1 half), batch stride 512*NPIX.
__global__ void dist_argmin_kernel(const float* __restrict__ f1out,
                                   const float* __restrict__ f2,
                                   const float* __restrict__ b2n,
                                   int* __restrict__ idxout) {
    const int BM = 128, BN = 128, TM = 8, TN = 8, BK = 8, CC = 256;
    __shared__ __align__(16) float As[BK][BM];
    __shared__ __align__(16) float Bs[BK][BN];
    __shared__ float rv[16][BM];
    __shared__ int ri[16][BM];

    int b = blockIdx.y;
    int i0 = blockIdx.x * BM;
    const float* Q = f1out + (long)b * 512 * NPIX;
    const float* Kf = f2 + (long)b * 256 * NPIX;
    const float* bn = b2n + (long)b * NPIX;
    int tid = threadIdx.x;
    int tx = tid & 15;
    int ty = tid >> 4;

    float bestv[TM];
    int besti[TM];
#pragma unroll
    for (int u = 0; u < TM; u++) {
        bestv[u] = 3.4e38f;
        besti[u] = 0;
    }

    for (int j0 = 0; j0 < NPIX; j0 += BN) {
        float acc[TM][TN];
#pragma unroll
        for (int u = 0; u < TM; u++)
#pragma unroll
            for (int v = 0; v < TN; v++) acc[u][v] = 0.f;

        for (int k0 = 0; k0 < CC; k0 += BK) {
#pragma unroll
            for (int t = tid; t < BM * BK; t += 256) {
                int m = t % BM;
                int k = t / BM;
                As[k][m] = Q[(long)(k0 + k) * NPIX + i0 + m];
            }
#pragma unroll
            for (int t = tid; t < BN * BK; t += 256) {
                int n = t % BN;
                int k = t / BN;
                Bs[k][n] = Kf[(long)(k0 + k) * NPIX + j0 + n];
            }
            __syncthreads();
#pragma unroll
            for (int kk = 0; kk < BK; kk++) {
                float a[TM], bv[TN];
#pragma unroll
                for (int u = 0; u < TM; u += 4)
                    *(float4*)&a[u] = *(const float4*)&As[kk][ty * TM + u];
#pragma unroll
                for (int v = 0; v < TN; v += 4)
                    *(float4*)&bv[v] = *(const float4*)&Bs[kk][tx * TN + v];
#pragma unroll
                for (int u = 0; u < TM; u++)
#pragma unroll
                    for (int v = 0; v < TN; v++) acc[u][v] += a[u] * bv[v];
            }
            __syncthreads();
        }
        // fold this j-tile into running argmin (per-thread j is monotonically
        // increasing, so strict < keeps the first/smallest index on ties)
#pragma unroll
        for (int v = 0; v < TN; v++) {
            int j = j0 + tx * TN + v;
            float bj = bn[j];
#pragma unroll
            for (int u = 0; u < TM; u++) {
                float d = bj - 2.f * acc[u][v];
                if (d < bestv[u]) {
                    bestv[u] = d;
                    besti[u] = j;
                }
            }
        }
    }
    // cross-thread reduction (16 tx lanes share each i)
#pragma unroll
    for (int u = 0; u < TM; u++) {
        rv[tx][ty * TM + u] = bestv[u];
        ri[tx][ty * TM + u] = besti[u];
    }
    __syncthreads();
    if (tid < BM) {
        float bv = rv[0][tid];
        int bi = ri[0][tid];
#pragma unroll
        for (int t = 1; t < 16; t++) {
            float v = rv[t][tid];
            int ii = ri[t][tid];
            if (v < bv || (v == bv && ii < bi)) {
                bv = v;
                bi = ii;
            }
        }
        idxout[(long)b * NPIX + i0 + tid] = bi;
    }
}

// ---------------- gather: out[b][256+c][i] = f2[b][c][idx[b][i]] ----------------
__global__ void gather_kernel(const float* __restrict__ f2, const int* __restrict__ idx,
                              float* __restrict__ out) {
    long t = (long)blockIdx.x * blockDim.x + threadIdx.x;
    if (t >= (long)NB * C3 * NPIX) return;
    int j = (int)(t & (NPIX - 1));
    int c = (int)((t >> 12) & 255);
    int b = (int)(t >> 20);
    int id = idx[(long)b * NPIX + j];
    out[((long)b * 512 + 256 + c) * NPIX + j] = f2[((long)b * C3 + c) * NPIX + id];
}

// ---------------- launch ----------------
extern "C" void kernel_launch(void* const* d_in, const int* in_sizes, int n_in,
                              void* d_out, int out_size) {
    const float* x1 = (const float*)d_in[0];
    const float* x2 = (const float*)d_in[1];
    const float* w1 = (const float*)d_in[2];
    const float* b1 = (const float*)d_in[3];
    const float* w2 = (const float*)d_in[4];
    const float* b2 = (const float*)d_in[5];
    const float* w3 = (const float*)d_in[6];
    const float* b3 = (const float*)d_in[7];
    float* out = (float*)d_out;

    float *T1, *T2, *F2, *B2N, *Wt2, *Wt3;
    int* IDX;
    cudaGetSymbolAddress((void**)&T1, g_T1);
    cudaGetSymbolAddress((void**)&T2, g_T2);
    cudaGetSymbolAddress((void**)&F2, g_F2);
    cudaGetSymbolAddress((void**)&B2N, g_B2N);
    cudaGetSymbolAddress((void**)&IDX, g_IDX);
    cudaGetSymbolAddress((void**)&Wt2, g_Wt2);
    cudaGetSymbolAddress((void**)&Wt3, g_Wt3);

    // weight transposes (k-major for coalesced GEMM A-tile loads)
    transpose_w_kernel<<<(C2 * 288 + 255) / 256, 256>>>(w2, Wt2, C2, 288);
    transpose_w_kernel<<<(C3 * 576 + 255) / 256, 256>>>(w3, Wt3, C3, 576);

    // features of x1 -> directly into out[:, 0:256] (batch stride 512*NPIX)
    conv1_kernel<<<dim3(NPIX / 256, NB), 256>>>(x1, w1, b1, T1);
    conv_gemm_kernel<64, 4><<<dim3(NPIX / 128, 1, NB), 256>>>(T1, C1, Wt2, 288, C2, b2, T2,
                                                              (long)C2 * NPIX);
    conv_gemm_kernel<128, 8><<<dim3(NPIX / 128, 2, NB), 256>>>(T2, C2, Wt3, 576, C3, b3, out,
                                                               (long)512 * NPIX);

    // features of x2 -> F2 scratch
    conv1_kernel<<<dim3(NPIX / 256, NB), 256>>>(x2, w1, b1, T1);
    conv_gemm_kernel<64, 4><<<dim3(NPIX / 128, 1, NB), 256>>>(T1, C1, Wt2, 288, C2, b2, T2,
                                                              (long)C2 * NPIX);
    conv_gemm_kernel<128, 8><<<dim3(NPIX / 128, 2, NB), 256>>>(T2, C2, Wt3, 576, C3, b3, F2,
                                                               (long)C3 * NPIX);

    // key norms, fused distance+argmin, gather
    rownorm_kernel<<<dim3(NPIX / 256, NB), 256>>>(F2, B2N);
    dist_argmin_kernel<<<dim3(NPIX / 128, NB), 256>>>(out, F2, B2N, IDX);
    gather_kernel<<<(int)(((long)NB * C3 * NPIX + 255) / 256), 256>>>(F2, IDX, out);
}

// round 2
// speedup vs baseline: 1.0013x; 1.0013x over previous
#include <cuda_runtime.h>

#define HH 64
#define WW 64
#define NPIX 4096
#define NB 4
#define C1 32
#define C2 64
#define C3 256

// ---------------- static device scratch (no allocations allowed) ----------------
__device__ float g_T1[NB * C1 * NPIX];     // conv1 out (reused for x1 then x2)
__device__ float g_T2[NB * C2 * NPIX];     // conv2 out
__device__ float g_F2[NB * C3 * NPIX];     // features of x2
__device__ float g_B2N[NB * NPIX];         // ||f2||^2 per key
__device__ int   g_IDX[NB * NPIX];         // argmin indices
__device__ float g_Wt2[288 * C2];          // w2 transposed to [k][co]
__device__ float g_Wt3[576 * C3];          // w3 transposed to [k][co]

// ---------------- weight transpose: w[co][k] -> wT[k][co] ----------------
__global__ void transpose_w_kernel(const float* __restrict__ w, float* __restrict__ wT,
                                   int CO, int K) {
    int t = blockIdx.x * blockDim.x + threadIdx.x;
    if (t < CO * K) {
        int co = t / K;
        int k = t - co * K;
        wT[k * CO + co] = w[t];
    }
}

// ---------------- conv1: 1 -> 32 channels, tiny direct conv ----------------
__global__ void conv1_kernel(const float* __restrict__ x, const float* __restrict__ w,
                             const float* __restrict__ bias, float* __restrict__ out) {
    int p = blockIdx.x * blockDim.x + threadIdx.x;
    int b = blockIdx.y;
    if (p >= NPIX) return;
    int y = p >> 6, xx = p & 63;
    const float* xb = x + (long)b * NPIX;
    float in[9];
#pragma unroll
    for (int ky = 0; ky < 3; ky++)
#pragma unroll
        for (int kx = 0; kx < 3; kx++) {
            int yy = y + ky - 1, xc = xx + kx - 1;
            in[ky * 3 + kx] =
                ((unsigned)yy < (unsigned)HH && (unsigned)xc < (unsigned)WW) ? xb[yy * WW + xc] : 0.f;
        }
#pragma unroll 4
    for (int co = 0; co < C1; co++) {
        float acc = bias[co];
#pragma unroll
        for (int t = 0; t < 9; t++) acc += w[co * 9 + t] * in[t];
        out[((long)b * C1 + co) * NPIX + p] = acc;
    }
}

// ---------------- implicit-GEMM conv: out[co][n] = sum_k wT[k][co] * patch[k][n] ----------------
// BN=128, TN=8, BK=8 fixed; BM/TM templated (conv2: 64/4, conv3: 128/8). 256 threads.
template <int BM, int TM>
__global__ void conv_gemm_kernel(const float* __restrict__ in, int CI,
                                 const float* __restrict__ wT, int Ktot, int CO,
                                 const float* __restrict__ bias,
                                 float* __restrict__ out, long outBatchStride) {
    const int BN = 128, TN = 8, BK = 8;
    __shared__ __align__(16) float As[BK][BM];
    __shared__ __align__(16) float Bs[BK][BN];
    int bb = blockIdx.z;
    int m0 = blockIdx.y * BM;
    int n0 = blockIdx.x * BN;
    int tid = threadIdx.x;
    int tx = tid & 15;
    int ty = tid >> 4;
    long inBase = (long)bb * CI * NPIX;

    float acc[TM][TN];
#pragma unroll
    for (int u = 0; u < TM; u++)
#pragma unroll
        for (int v = 0; v < TN; v++) acc[u][v] = 0.f;

    for (int k0 = 0; k0 < Ktot; k0 += BK) {
        // A tile: weights (coalesced, conflict-free)
#pragma unroll
        for (int t = tid; t < BM * BK; t += 256) {
            int m = t % BM;
            int k = t / BM;
            As[k][m] = wT[(long)(k0 + k) * CO + m0 + m];
        }
        // B tile: implicit im2col patches
#pragma unroll
        for (int t = tid; t < BN * BK; t += 256) {
            int n = t % BN;
            int k = t / BN;
            int gk = k0 + k;
            int ci = gk / 9;
            int tap = gk - ci * 9;
            int ky = tap / 3 - 1;
            int kx = tap - (tap / 3) * 3 - 1;
            int gp = n0 + n;
            int y = (gp >> 6) + ky;
            int x = (gp & 63) + kx;
            float v = 0.f;
            if ((unsigned)y < (unsigned)HH && (unsigned)x < (unsigned)WW)
                v = in[inBase + (long)ci * NPIX + (y << 6) + x];
            Bs[k][n] = v;
        }
        __syncthreads();
#pragma unroll
        for (int kk = 0; kk < BK; kk++) {
            float a[TM], bv[TN];
#pragma unroll
            for (int u = 0; u < TM; u += 4)
                *(float4*)&a[u] = *(const float4*)&As[kk][ty * TM + u];
#pragma unroll
            for (int v = 0; v < TN; v += 4)
                *(float4*)&bv[v] = *(const float4*)&Bs[kk][tx * TN + v];
#pragma unroll
            for (int u = 0; u < TM; u++)
#pragma unroll
                for (int v = 0; v < TN; v++) acc[u][v] += a[u] * bv[v];
        }
        __syncthreads();
    }
#pragma unroll
    for (int u = 0; u < TM; u++) {
        int m = m0 + ty * TM + u;
        float bval = bias[m];
        long base = (long)bb * outBatchStride + (long)m * NPIX + n0 + tx * TN;
#pragma unroll
        for (int v = 0; v < TN; v += 4) {
            float4 o;
            o.x = acc[u][v + 0] + bval;
            o.y = acc[u][v + 1] + bval;
            o.z = acc[u][v + 2] + bval;
            o.w = acc[u][v + 3] + bval;
            *(float4*)&out[base + v] = o;
        }
    }
}

// ---------------- key row norms: b2n[b][j] = sum_c f2[b][c][j]^2 ----------------
__global__ void rownorm_kernel(const float* __restrict__ f2, float* __restrict__ b2n) {
    int j = blockIdx.x * blockDim.x + threadIdx.x;
    int b = blockIdx.y;
    if (j >= NPIX) return;
    const float* p = f2 + (long)b * C3 * NPIX + j;
    float s = 0.f;
#pragma unroll 8
    for (int c = 0; c < C3; c++) {
        float v = p[(long)c * NPIX];
        s += v * v;
    }
    b2n[(long)b * NPIX + j] = s;
}

// ---------------- fused distance GEMM + argmin ----------------
// dist(i,j) = b2n[j] - 2 * sum_c Q[c][i] * K[c][j]  (a2 term constant per row)
// Q read from d_out (f1 half), batch stride 512*NPIX.
__global__ void dist_argmin_kernel(const float* __restrict__ f1out,
                                   const float* __restrict__ f2,
                                   const float* __restrict__ b2n,
                                   int* __restrict__ idxout) {
    const int BM = 128, BN = 128, TM = 8, TN = 8, BK = 8, CC = 256;
    __shared__ __align__(16) float As[BK][BM];
    __shared__ __align__(16) float Bs[BK][BN];
    __shared__ float rv[16][BM];
    __shared__ int ri[16][BM];

    int b = blockIdx.y;
    int i0 = blockIdx.x * BM;
    const float* Q = f1out + (long)b * 512 * NPIX;
    const float* Kf = f2 + (long)b * 256 * NPIX;
    const float* bn = b2n + (long)b * NPIX;
    int tid = threadIdx.x;
    int tx = tid & 15;
    int ty = tid >> 4;

    float bestv[TM];
    int besti[TM];
#pragma unroll
    for (int u = 0; u < TM; u++) {
        bestv[u] = 3.4e38f;
        besti[u] = 0;
    }

    for (int j0 = 0; j0 < NPIX; j0 += BN) {
        float acc[TM][TN];
#pragma unroll
        for (int u = 0; u < TM; u++)
#pragma unroll
            for (int v = 0; v < TN; v++) acc[u][v] = 0.f;

        for (int k0 = 0; k0 < CC; k0 += BK) {
#pragma unroll
            for (int t = tid; t < BM * BK; t += 256) {
                int m = t % BM;
                int k = t / BM;
                As[k][m] = Q[(long)(k0 + k) * NPIX + i0 + m];
            }
#pragma unroll
            for (int t = tid; t < BN * BK; t += 256) {
                int n = t % BN;
                int k = t / BN;
                Bs[k][n] = Kf[(long)(k0 + k) * NPIX + j0 + n];
            }
            __syncthreads();
#pragma unroll
            for (int kk = 0; kk < BK; kk++) {
                float a[TM], bv[TN];
#pragma unroll
                for (int u = 0; u < TM; u += 4)
                    *(float4*)&a[u] = *(const float4*)&As[kk][ty * TM + u];
#pragma unroll
                for (int v = 0; v < TN; v += 4)
                    *(float4*)&bv[v] = *(const float4*)&Bs[kk][tx * TN + v];
#pragma unroll
                for (int u = 0; u < TM; u++)
#pragma unroll
                    for (int v = 0; v < TN; v++) acc[u][v] += a[u] * bv[v];
            }
            __syncthreads();
        }
        // fold this j-tile into running argmin (per-thread j is monotonically
        // increasing, so strict < keeps the first/smallest index on ties)
#pragma unroll
        for (int v = 0; v < TN; v++) {
            int j = j0 + tx * TN + v;
            float bj = bn[j];
#pragma unroll
            for (int u = 0; u < TM; u++) {
                float d = bj - 2.f * acc[u][v];
                if (d < bestv[u]) {
                    bestv[u] = d;
                    besti[u] = j;
                }
            }
        }
    }
    // cross-thread reduction (16 tx lanes share each i)
#pragma unroll
    for (int u = 0; u < TM; u++) {
        rv[tx][ty * TM + u] = bestv[u];
        ri[tx][ty * TM + u] = besti[u];
    }
    __syncthreads();
    if (tid < BM) {
        float bv = rv[0][tid];
        int bi = ri[0][tid];
#pragma unroll
        for (int t = 1; t < 16; t++) {
            float v = rv[t][tid];
            int ii = ri[t][tid];
            if (v < bv || (v == bv && ii < bi)) {
                bv = v;
                bi = ii;
            }
        }
        idxout[(long)b * NPIX + i0 + tid] = bi;
    }
}

// ---------------- gather: out[b][256+c][i] = f2[b][c][idx[b][i]] ----------------
__global__ void gather_kernel(const float* __restrict__ f2, const int* __restrict__ idx,
                              float* __restrict__ out) {
    long t = (long)blockIdx.x * blockDim.x + threadIdx.x;
    if (t >= (long)NB * C3 * NPIX) return;
    int j = (int)(t & (NPIX - 1));
    int c = (int)((t >> 12) & 255);
    int b = (int)(t >> 20);
    int id = idx[(long)b * NPIX + j];
    out[((long)b * 512 + 256 + c) * NPIX + j] = f2[((long)b * C3 + c) * NPIX + id];
}

// ---------------- launch ----------------
extern "C" void kernel_launch(void* const* d_in, const int* in_sizes, int n_in,
                              void* d_out, int out_size) {
    const float* x1 = (const float*)d_in[0];
    const float* x2 = (const float*)d_in[1];
    const float* w1 = (const float*)d_in[2];
    const float* b1 = (const float*)d_in[3];
    const float* w2 = (const float*)d_in[4];
    const float* b2 = (const float*)d_in[5];
    const float* w3 = (const float*)d_in[6];
    const float* b3 = (const float*)d_in[7];
    float* out = (float*)d_out;

    float *T1, *T2, *F2, *B2N, *Wt2, *Wt3;
    int* IDX;
    cudaGetSymbolAddress((void**)&T1, g_T1);
    cudaGetSymbolAddress((void**)&T2, g_T2);
    cudaGetSymbolAddress((void**)&F2, g_F2);
    cudaGetSymbolAddress((void**)&B2N, g_B2N);
    cudaGetSymbolAddress((void**)&IDX, g_IDX);
    cudaGetSymbolAddress((void**)&Wt2, g_Wt2);
    cudaGetSymbolAddress((void**)&Wt3, g_Wt3);

    // weight transposes (k-major for coalesced GEMM A-tile loads)
    transpose_w_kernel<<<(C2 * 288 + 255) / 256, 256>>>(w2, Wt2, C2, 288);
    transpose_w_kernel<<<(C3 * 576 + 255) / 256, 256>>>(w3, Wt3, C3, 576);

    // features of x1 -> directly into out[:, 0:256] (batch stride 512*NPIX)
    conv1_kernel<<<dim3(NPIX / 256, NB), 256>>>(x1, w1, b1, T1);
    conv_gemm_kernel<64, 4><<<dim3(NPIX / 128, 1, NB), 256>>>(T1, C1, Wt2, 288, C2, b2, T2,
                                                              (long)C2 * NPIX);
    conv_gemm_kernel<128, 8><<<dim3(NPIX / 128, 2, NB), 256>>>(T2, C2, Wt3, 576, C3, b3, out,
                                                               (long)512 * NPIX);

    // features of x2 -> F2 scratch
    conv1_kernel<<<dim3(NPIX / 256, NB), 256>>>(x2, w1, b1, T1);
    conv_gemm_kernel<64, 4><<<dim3(NPIX / 128, 1, NB), 256>>>(T1, C1, Wt2, 288, C2, b2, T2,
                                                              (long)C2 * NPIX);
    conv_gemm_kernel<128, 8><<<dim3(NPIX / 128, 2, NB), 256>>>(T2, C2, Wt3, 576, C3, b3, F2,
                                                               (long)C3 * NPIX);

    // key norms, fused distance+argmin, gather
    rownorm_kernel<<<dim3(NPIX / 256, NB), 256>>>(F2, B2N);
    dist_argmin_kernel<<<dim3(NPIX / 128, NB), 256>>>(out, F2, B2N, IDX);
    gather_kernel<<<(int)(((long)NB * C3 * NPIX + 255) / 256), 256>>>(F2, IDX, out);
}

// round 4
// speedup vs baseline: 1.8990x; 1.8964x over previous
#include <cuda_runtime.h>
#include <cstdint>

#define HH 64
#define WW 64
#define NPIX 4096
#define NB 4
#define C1 32
#define C2 64
#define C3 256

typedef unsigned long long ull;

// ---------------- packed f32x2 helpers ----------------
__device__ __forceinline__ ull dup2(float v) {
    unsigned int b = __float_as_uint(v);
    return ((ull)b << 32) | (ull)b;
}
__device__ __forceinline__ void ffma2(ull& acc, ull a, ull b) {
    asm("fma.rn.f32x2 %0, %1, %2, %0;" : "+l"(acc) : "l"(a), "l"(b));
}
__device__ __forceinline__ float lo32(ull x) { return __uint_as_float((unsigned int)x); }
__device__ __forceinline__ float hi32(ull x) { return __uint_as_float((unsigned int)(x >> 32)); }

// ---------------- static device scratch ----------------
__device__ float g_T1[2 * NB * C1 * NPIX];
__device__ float g_T2[2 * NB * C2 * NPIX];
__device__ float g_F2[NB * C3 * NPIX];
__device__ float g_B2N[NB * NPIX];
__device__ int g_IDX[NB * NPIX];
__device__ float g_Wt2[288 * C2];
__device__ float g_Wt3[576 * C3];

// ---------------- prep: both weight transposes ----------------
__global__ void prep_kernel(const float* __restrict__ w2, const float* __restrict__ w3,
                            float* __restrict__ Wt2, float* __restrict__ Wt3) {
    int t = blockIdx.x * blockDim.x + threadIdx.x;
    if (t < C2 * 288) {
        int co = t / 288, k = t - co * 288;
        Wt2[k * C2 + co] = w2[t];
    } else {
        int u = t - C2 * 288;
        if (u < C3 * 576) {
            int co = u / 576, k = u - co * 576;
            Wt3[k * C3 + co] = w3[u];
        }
    }
}

// ---------------- conv1: both inputs, grid.y = 8 ----------------
__global__ void conv1_kernel(const float* __restrict__ x1, const float* __restrict__ x2,
                             const float* __restrict__ w, const float* __restrict__ bias,
                             float* __restrict__ out) {
    int p = blockIdx.x * blockDim.x + threadIdx.x;
    int z = blockIdx.y;
    if (p >= NPIX) return;
    const float* x = (z >> 2) ? x2 : x1;
    int b = z & 3;
    int y = p >> 6, xx = p & 63;
    const float* xb = x + (long)b * NPIX;
    float in[9];
#pragma unroll
    for (int ky = 0; ky < 3; ky++)
#pragma unroll
        for (int kx = 0; kx < 3; kx++) {
            int yy = y + ky - 1, xc = xx + kx - 1;
            in[ky * 3 + kx] =
                ((unsigned)yy < (unsigned)HH && (unsigned)xc < (unsigned)WW) ? xb[yy * WW + xc] : 0.f;
        }
#pragma unroll 4
    for (int co = 0; co < C1; co++) {
        float acc = bias[co];
#pragma unroll
        for (int t = 0; t < 9; t++) acc += w[co * 9 + t] * in[t];
        out[((long)z * C1 + co) * NPIX + p] = acc;
    }
}

// ---------------- implicit-GEMM conv with packed f32x2 (grid.z = 8) ----------------
template <int BM, int TM>
__global__ void conv_gemm_kernel(const float* __restrict__ in, int CI,
                                 const float* __restrict__ wT, int Ktot, int CO,
                                 const float* __restrict__ bias,
                                 float* __restrict__ outA, long strideA,
                                 float* __restrict__ outB, long strideB) {
    const int BN = 128, TN = 8, BK = 16;
    __shared__ __align__(16) ull As2[BK][BM];     // duplicated (a,a) weights
    __shared__ __align__(16) float Bs[BK][BN];
    int z = blockIdx.z;
    int sel = z >> 2, bb = z & 3;
    float* out = sel ? outB : outA;
    long os = sel ? strideB : strideA;
    int m0 = blockIdx.y * BM;
    int n0 = blockIdx.x * BN;
    int tid = threadIdx.x;
    int tx = tid & 15, ty = tid >> 4;
    long inBase = (long)z * CI * NPIX;

    ull acc[TM][TN / 2];
#pragma unroll
    for (int u = 0; u < TM; u++)
#pragma unroll
        for (int v = 0; v < TN / 2; v++) acc[u][v] = 0ull;

    for (int k0 = 0; k0 < Ktot; k0 += BK) {
        // A tile: weights, duplicated-packed
#pragma unroll
        for (int e4 = tid; e4 < BM * BK / 4; e4 += 256) {
            int k = e4 / (BM / 4);
            int m4 = e4 % (BM / 4);
            float4 v = *(const float4*)(wT + (long)(k0 + k) * CO + m0 + m4 * 4);
            ull* d = &As2[k][m4 * 4];
            d[0] = dup2(v.x);
            d[1] = dup2(v.y);
            d[2] = dup2(v.z);
            d[3] = dup2(v.w);
        }
        // B tile: implicit im2col
#pragma unroll
        for (int t = tid; t < BN * BK; t += 256) {
            int n = t & 127;
            int k = t >> 7;
            int gk = k0 + k;
            int ci = gk / 9, tap = gk - ci * 9;
            int kyy = tap / 3 - 1, kxx = tap - (tap / 3) * 3 - 1;
            int gp = n0 + n;
            int y = (gp >> 6) + kyy, x = (gp & 63) + kxx;
            float v = 0.f;
            if ((unsigned)y < (unsigned)HH && (unsigned)x < (unsigned)WW)
                v = in[inBase + (long)ci * NPIX + (y << 6) + x];
            Bs[k][n] = v;
        }
        __syncthreads();
#pragma unroll
        for (int kk = 0; kk < BK; kk++) {
            ull a2[TM];
#pragma unroll
            for (int u = 0; u < TM; u += 2) {
                ulonglong2 t = *(const ulonglong2*)&As2[kk][ty * TM + u];
                a2[u] = t.x;
                a2[u + 1] = t.y;
            }
            ull b2r[4];
            {
                ulonglong2 t0 = *(const ulonglong2*)&Bs[kk][tx * TN];
                ulonglong2 t1 = *(const ulonglong2*)&Bs[kk][tx * TN + 4];
                b2r[0] = t0.x;
                b2r[1] = t0.y;
                b2r[2] = t1.x;
                b2r[3] = t1.y;
            }
#pragma unroll
            for (int u = 0; u < TM; u++)
#pragma unroll
                for (int vp = 0; vp < 4; vp++) ffma2(acc[u][vp], a2[u], b2r[vp]);
        }
        __syncthreads();
    }
#pragma unroll
    for (int u = 0; u < TM; u++) {
        int m = m0 + ty * TM + u;
        float bval = bias[m];
        long base = (long)bb * os + (long)m * NPIX + n0 + tx * TN;
        float4 o0, o1;
        o0.x = lo32(acc[u][0]) + bval;
        o0.y = hi32(acc[u][0]) + bval;
        o0.z = lo32(acc[u][1]) + bval;
        o0.w = hi32(acc[u][1]) + bval;
        o1.x = lo32(acc[u][2]) + bval;
        o1.y = hi32(acc[u][2]) + bval;
        o1.z = lo32(acc[u][3]) + bval;
        o1.w = hi32(acc[u][3]) + bval;
        *(float4*)&out[base] = o0;
        *(float4*)&out[base + 4] = o1;
    }
}

// ---------------- key row norms ----------------
__global__ void rownorm_kernel(const float* __restrict__ f2, float* __restrict__ b2n) {
    int j = blockIdx.x * blockDim.x + threadIdx.x;
    int b = blockIdx.y;
    if (j >= NPIX) return;
    const float* p = f2 + (long)b * C3 * NPIX + j;
    float s = 0.f;
#pragma unroll 8
    for (int c = 0; c < C3; c++) {
        float v = p[(long)c * NPIX];
        s += v * v;
    }
    b2n[(long)b * NPIX + j] = s;
}

// ---------------- fused distance GEMM + argmin, packed f32x2 ----------------
__global__ void __launch_bounds__(256)
dist_argmin_kernel(const float* __restrict__ f1out, const float* __restrict__ f2,
                   const float* __restrict__ b2n, int* __restrict__ idxout) {
    const int BM = 128, BN = 128, BK = 16, TM = 8, TN = 8;
    __shared__ __align__(16) ull As2[BK][BM];
    __shared__ __align__(16) float Bs[BK][BN];
    __shared__ float rv[16][BM];
    __shared__ int ri[16][BM];

    int b = blockIdx.y;
    int i0 = blockIdx.x * BM;
    const float* Q = f1out + (long)b * 512 * NPIX;
    const float* Kf = f2 + (long)b * 256 * NPIX;
    const float* bn = b2n + (long)b * NPIX;
    int tid = threadIdx.x;
    int tx = tid & 15, ty = tid >> 4;

    float bestv[TM];
    int besti[TM];
#pragma unroll
    for (int u = 0; u < TM; u++) {
        bestv[u] = 3.4e38f;
        besti[u] = 0;
    }

    for (int j0 = 0; j0 < NPIX; j0 += BN) {
        ull acc[TM][TN / 2];
#pragma unroll
        for (int u = 0; u < TM; u++)
#pragma unroll
            for (int v = 0; v < TN / 2; v++) acc[u][v] = 0ull;

        for (int k0 = 0; k0 < C3; k0 += BK) {
#pragma unroll
            for (int i = 0; i < 2; i++) {
                int e = tid + i * 256;
                int k = e >> 5, m4 = e & 31;
                float4 v = *(const float4*)(Q + (long)(k0 + k) * NPIX + i0 + m4 * 4);
                ull* d = &As2[k][m4 * 4];
                d[0] = dup2(v.x);
                d[1] = dup2(v.y);
                d[2] = dup2(v.z);
                d[3] = dup2(v.w);
            }
#pragma unroll
            for (int i = 0; i < 2; i++) {
                int e = tid + i * 256;
                int k = e >> 5, n4 = e & 31;
                *(float4*)&Bs[k][n4 * 4] =
                    *(const float4*)(Kf + (long)(k0 + k) * NPIX + j0 + n4 * 4);
            }
            __syncthreads();
#pragma unroll
            for (int kk = 0; kk < BK; kk++) {
                ull a2[TM];
#pragma unroll
                for (int u = 0; u < TM; u += 2) {
                    ulonglong2 t = *(const ulonglong2*)&As2[kk][ty * TM + u];
                    a2[u] = t.x;
                    a2[u + 1] = t.y;
                }
                ull b2r[4];
                {
                    ulonglong2 t0 = *(const ulonglong2*)&Bs[kk][tx * TN];
                    ulonglong2 t1 = *(const ulonglong2*)&Bs[kk][tx * TN + 4];
                    b2r[0] = t0.x;
                    b2r[1] = t0.y;
                    b2r[2] = t1.x;
                    b2r[3] = t1.y;
                }
#pragma unroll
                for (int u = 0; u < TM; u++)
#pragma unroll
                    for (int vp = 0; vp < 4; vp++) ffma2(acc[u][vp], a2[u], b2r[vp]);
            }
            __syncthreads();
        }
        // fold tile into running argmin (j ascending per thread; strict < keeps first index)
#pragma unroll
        for (int vp = 0; vp < 4; vp++) {
            int j = j0 + tx * TN + vp * 2;
            float bj0 = bn[j];
            float bj1 = bn[j + 1];
#pragma unroll
            for (int u = 0; u < TM; u++) {
                float d0 = bj0 - 2.f * lo32(acc[u][vp]);
                if (d0 < bestv[u]) {
                    bestv[u] = d0;
                    besti[u] = j;
                }
                float d1 = bj1 - 2.f * hi32(acc[u][vp]);
                if (d1 < bestv[u]) {
                    bestv[u] = d1;
                    besti[u] = j + 1;
                }
            }
        }
    }
    // cross-thread reduction (16 tx lanes share each i)
#pragma unroll
    for (int u = 0; u < TM; u++) {
        rv[tx][ty * TM + u] = bestv[u];
        ri[tx][ty * TM + u] = besti[u];
    }
    __syncthreads();
    if (tid < BM) {
        float bv = rv[0][tid];
        int bi = ri[0][tid];
#pragma unroll
        for (int t = 1; t < 16; t++) {
            float v = rv[t][tid];
            int ii = ri[t][tid];
            if (v < bv || (v == bv && ii < bi)) {
                bv = v;
                bi = ii;
            }
        }
        idxout[(long)b * NPIX + i0 + tid] = bi;
    }
}

// ---------------- gather ----------------
__global__ void gather_kernel(const float* __restrict__ f2, const int* __restrict__ idx,
                              float* __restrict__ out) {
    long t = (long)blockIdx.x * blockDim.x + threadIdx.x;
    if (t >= (long)NB * C3 * NPIX) return;
    int j = (int)(t & (NPIX - 1));
    int c = (int)((t >> 12) & 255);
    int b = (int)(t >> 20);
    int id = idx[(long)b * NPIX + j];
    out[((long)b * 512 + 256 + c) * NPIX + j] = f2[((long)b * C3 + c) * NPIX + id];
}

// ---------------- launch ----------------
extern "C" void kernel_launch(void* const* d_in, const int* in_sizes, int n_in,
                              void* d_out, int out_size) {
    const float* x1 = (const float*)d_in[0];
    const float* x2 = (const float*)d_in[1];
    const float* w1 = (const float*)d_in[2];
    const float* b1 = (const float*)d_in[3];
    const float* w2 = (const float*)d_in[4];
    const float* b2 = (const float*)d_in[5];
    const float* w3 = (const float*)d_in[6];
    const float* b3 = (const float*)d_in[7];
    float* out = (float*)d_out;

    float *T1, *T2, *F2, *B2N, *Wt2, *Wt3;
    int* IDX;
    cudaGetSymbolAddress((void**)&T1, g_T1);
    cudaGetSymbolAddress((void**)&T2, g_T2);
    cudaGetSymbolAddress((void**)&F2, g_F2);
    cudaGetSymbolAddress((void**)&B2N, g_B2N);
    cudaGetSymbolAddress((void**)&IDX, g_IDX);
    cudaGetSymbolAddress((void**)&Wt2, g_Wt2);
    cudaGetSymbolAddress((void**)&Wt3, g_Wt3);

    prep_kernel<<<(C2 * 288 + C3 * 576 + 255) / 256, 256>>>(w2, w3, Wt2, Wt3);
    conv1_kernel<<<dim3(NPIX / 256, 8), 256>>>(x1, x2, w1, b1, T1);
    conv_gemm_kernel<64, 4><<<dim3(NPIX / 128, 1, 8), 256>>>(
        T1, C1, Wt2, 288, C2, b2, T2, (long)C2 * NPIX, T2 + (long)NB * C2 * NPIX,
        (long)C2 * NPIX);
    conv_gemm_kernel<128, 8><<<dim3(NPIX / 128, 2, 8), 256>>>(
        T2, C2, Wt3, 576, C3, b3, out, (long)512 * NPIX, F2, (long)C3 * NPIX);
    rownorm_kernel<<<dim3(NPIX / 256, NB), 256>>>(F2, B2N);
    dist_argmin_kernel<<<dim3(NPIX / 128, NB), 256>>>(out, F2, B2N, IDX);
    gather_kernel<<<(int)(((long)NB * C3 * NPIX + 255) / 256), 256>>>(F2, IDX, out);
}

// round 5
// speedup vs baseline: 1.9169x; 1.0095x over previous
#include <cuda_runtime.h>
#include <cstdint>

#define HH 64
#define WW 64
#define NPIX 4096
#define NB 4
#define C1 32
#define C2 64
#define C3 256

typedef unsigned long long ull;

__device__ __forceinline__ ull dup2(float v) {
    ull r;
    asm("mov.b64 %0, {%1, %1};" : "=l"(r) : "r"(__float_as_uint(v)));
    return r;
}
__device__ __forceinline__ void ffma2(ull& acc, ull a, ull b) {
    asm("fma.rn.f32x2 %0, %1, %2, %0;" : "+l"(acc) : "l"(a), "l"(b));
}
__device__ __forceinline__ float lo32(ull x) { return __uint_as_float((unsigned int)x); }
__device__ __forceinline__ float hi32(ull x) { return __uint_as_float((unsigned int)(x >> 32)); }

// ---------------- static device scratch ----------------
__device__ float g_T1[2 * NB * C1 * NPIX];
__device__ float g_T2[2 * NB * C2 * NPIX];
__device__ float g_F2[NB * C3 * NPIX];
__device__ float g_B2N[NB * NPIX];
__device__ int g_IDX[NB * NPIX];
__device__ float g_Wt2[288 * C2];
__device__ float g_Wt3[576 * C3];

// ---------------- prep: weight transposes ----------------
__global__ void prep_kernel(const float* __restrict__ w2, const float* __restrict__ w3,
                            float* __restrict__ Wt2, float* __restrict__ Wt3) {
    int t = blockIdx.x * blockDim.x + threadIdx.x;
    if (t < C2 * 288) {
        int co = t / 288, k = t - co * 288;
        Wt2[k * C2 + co] = w2[t];
    } else {
        int u = t - C2 * 288;
        if (u < C3 * 576) {
            int co = u / 576, k = u - co * 576;
            Wt3[k * C3 + co] = w3[u];
        }
    }
}

// ---------------- conv1 ----------------
__global__ void conv1_kernel(const float* __restrict__ x1, const float* __restrict__ x2,
                             const float* __restrict__ w, const float* __restrict__ bias,
                             float* __restrict__ out) {
    int p = blockIdx.x * blockDim.x + threadIdx.x;
    int z = blockIdx.y;
    if (p >= NPIX) return;
    const float* x = (z >> 2) ? x2 : x1;
    int b = z & 3;
    int y = p >> 6, xx = p & 63;
    const float* xb = x + (long)b * NPIX;
    float in[9];
#pragma unroll
    for (int ky = 0; ky < 3; ky++)
#pragma unroll
        for (int kx = 0; kx < 3; kx++) {
            int yy = y + ky - 1, xc = xx + kx - 1;
            in[ky * 3 + kx] =
                ((unsigned)yy < (unsigned)HH && (unsigned)xc < (unsigned)WW) ? xb[yy * WW + xc] : 0.f;
        }
#pragma unroll 4
    for (int co = 0; co < C1; co++) {
        float acc = bias[co];
#pragma unroll
        for (int t = 0; t < 9; t++) acc += w[co * 9 + t] * in[t];
        out[((long)z * C1 + co) * NPIX + p] = acc;
    }
}

// ---------------- implicit-GEMM conv: 512 thr, BN=128, BK=16, double-buffered ----------------
template <int BM, int TM>
__global__ void __launch_bounds__(512, 1)
conv_gemm_kernel(const float* __restrict__ in, int CI, const float* __restrict__ wT,
                 int Ktot, int CO, const float* __restrict__ bias,
                 float* __restrict__ outA, long strideA, float* __restrict__ outB, long strideB) {
    const int BK = 16;
    __shared__ __align__(16) ull As2[2][BK][BM];
    __shared__ __align__(16) float Bs[2][BK][128];
    int z = blockIdx.z;
    int sel = z >> 2, bb = z & 3;
    float* out = sel ? outB : outA;
    long os = sel ? strideB : strideA;
    int m0 = blockIdx.y * BM;
    int n0 = blockIdx.x * 128;
    int tid = threadIdx.x;
    int tx = tid & 15, ty = tid >> 4;
    long inBase = (long)z * CI * NPIX;
    const int NP2 = BM / 64;  // float2 A loads per thread

    float2 avr[NP2];
    float bvr[4];
    int nch = Ktot / BK;

    ull acc[TM][4];
#pragma unroll
    for (int u = 0; u < TM; u++)
#pragma unroll
        for (int v = 0; v < 4; v++) acc[u][v] = 0ull;

    auto loadA = [&](int c) {
        int k0 = c * BK;
#pragma unroll
        for (int i = 0; i < NP2; i++) {
            int e2 = tid + i * 512;
            int k = e2 / (BM / 2), p = e2 % (BM / 2);
            avr[i] = *(const float2*)&wT[(long)(k0 + k) * CO + m0 + p * 2];
        }
    };
    auto loadB = [&](int c) {
        int k0 = c * BK;
#pragma unroll
        for (int i = 0; i < 4; i++) {
            int e = tid + i * 512;
            int k = e >> 7, n = e & 127;
            int gk = k0 + k;
            int ci = gk / 9, tap = gk - ci * 9;
            int kyy = tap / 3 - 1, kxx = tap - (tap / 3) * 3 - 1;
            int gp = n0 + n;
            int y = (gp >> 6) + kyy, x = (gp & 63) + kxx;
            float v = 0.f;
            if ((unsigned)y < (unsigned)HH && (unsigned)x < (unsigned)WW)
                v = in[inBase + (long)ci * NPIX + (y << 6) + x];
            bvr[i] = v;
        }
    };
    auto store = [&](int buf) {
#pragma unroll
        for (int i = 0; i < NP2; i++) {
            int e2 = tid + i * 512;
            int k = e2 / (BM / 2), p = e2 % (BM / 2);
            As2[buf][k][p * 2] = dup2(avr[i].x);
            As2[buf][k][p * 2 + 1] = dup2(avr[i].y);
        }
#pragma unroll
        for (int i = 0; i < 4; i++) {
            int e = tid + i * 512;
            Bs[buf][e >> 7][e & 127] = bvr[i];
        }
    };

    loadA(0); loadB(0);
    store(0);
    if (nch > 1) { loadA(1); loadB(1); }
    __syncthreads();

    for (int c = 0; c < nch; c++) {
        int cur = c & 1;
        if (c + 1 < nch) {
            store(1 - cur);
            if (c + 2 < nch) { loadA(c + 2); loadB(c + 2); }
        }
#pragma unroll
        for (int kk = 0; kk < BK; kk++) {
            ull a2[TM];
#pragma unroll
            for (int u = 0; u < TM; u += 2) {
                ulonglong2 t = *(const ulonglong2*)&As2[cur][kk][ty * TM + u];
                a2[u] = t.x;
                a2[u + 1] = t.y;
            }
            ulonglong2 b0 = *(const ulonglong2*)&Bs[cur][kk][tx * 4];
            ulonglong2 b1 = *(const ulonglong2*)&Bs[cur][kk][64 + tx * 4];
#pragma unroll
            for (int u = 0; u < TM; u++) {
                ffma2(acc[u][0], a2[u], b0.x);
                ffma2(acc[u][1], a2[u], b0.y);
                ffma2(acc[u][2], a2[u], b1.x);
                ffma2(acc[u][3], a2[u], b1.y);
            }
        }
        __syncthreads();
    }
#pragma unroll
    for (int u = 0; u < TM; u++) {
        int m = m0 + ty * TM + u;
        float bval = bias[m];
        long base = (long)bb * os + (long)m * NPIX + n0;
        float4 o;
        o.x = lo32(acc[u][0]) + bval;
        o.y = hi32(acc[u][0]) + bval;
        o.z = lo32(acc[u][1]) + bval;
        o.w = hi32(acc[u][1]) + bval;
        *(float4*)&out[base + tx * 4] = o;
        o.x = lo32(acc[u][2]) + bval;
        o.y = hi32(acc[u][2]) + bval;
        o.z = lo32(acc[u][3]) + bval;
        o.w = hi32(acc[u][3]) + bval;
        *(float4*)&out[base + 64 + tx * 4] = o;
    }
}

// ---------------- key row norms ----------------
__global__ void rownorm_kernel(const float* __restrict__ f2, float* __restrict__ b2n) {
    int j = blockIdx.x * blockDim.x + threadIdx.x;
    int b = blockIdx.y;
    if (j >= NPIX) return;
    const float* p = f2 + (long)b * C3 * NPIX + j;
    float s = 0.f;
#pragma unroll 8
    for (int c = 0; c < C3; c++) {
        float v = p[(long)c * NPIX];
        s += v * v;
    }
    b2n[(long)b * NPIX + j] = s;
}

// ---------------- fused distance GEMM + argmin ----------------
// 512 threads, BM=128 (TM=4), BN=128, BK=16, double-buffered, strip-mined B.
__global__ void __launch_bounds__(512, 1)
dist_argmin_kernel(const float* __restrict__ f1out, const float* __restrict__ f2,
                   const float* __restrict__ b2n, int* __restrict__ idxout) {
    const int BK = 16, TM = 4;
    __shared__ __align__(16) ull As2[2][BK][128];
    __shared__ __align__(16) float Bs[2][BK][128];

    int b = blockIdx.y;
    int i0 = blockIdx.x * 128;
    const float* Q = f1out + (long)b * 512 * NPIX;
    const float* Kf = f2 + (long)b * 256 * NPIX;
    const float* bn = b2n + (long)b * NPIX;
    int tid = threadIdx.x;
    int tx = tid & 15, ty = tid >> 4;
    int lk = tid >> 5, lm4 = tid & 31;

    float bestv[TM];
    int besti[TM];
#pragma unroll
    for (int u = 0; u < TM; u++) { bestv[u] = 3.4e38f; besti[u] = 0; }

    ull acc[TM][4];
#pragma unroll
    for (int u = 0; u < TM; u++)
#pragma unroll
        for (int v = 0; v < 4; v++) acc[u][v] = 0ull;

    float4 av, bv;
    auto ldA = [&](int c) {
        int k0 = (c & 15) * BK;
        av = *(const float4*)&Q[(long)(k0 + lk) * NPIX + i0 + lm4 * 4];
    };
    auto ldB = [&](int c) {
        int j0 = (c >> 4) * 128, k0 = (c & 15) * BK;
        bv = *(const float4*)&Kf[(long)(k0 + lk) * NPIX + j0 + lm4 * 4];
    };
    auto stc = [&](int buf) {
        As2[buf][lk][lm4 * 4 + 0] = dup2(av.x);
        As2[buf][lk][lm4 * 4 + 1] = dup2(av.y);
        As2[buf][lk][lm4 * 4 + 2] = dup2(av.z);
        As2[buf][lk][lm4 * 4 + 3] = dup2(av.w);
        *(float4*)&Bs[buf][lk][lm4 * 4] = bv;
    };

    const int NCH = 512;  // 32 j-tiles * 16 k-chunks
    ldA(0); ldB(0);
    stc(0);
    ldA(1); ldB(1);
    __syncthreads();

    for (int c = 0; c < NCH; c++) {
        int cur = c & 1;
        if (c + 1 < NCH) {
            stc(1 - cur);
            if (c + 2 < NCH) { ldA(c + 2); ldB(c + 2); }
        }
#pragma unroll
        for (int kk = 0; kk < BK; kk++) {
            ull a2[TM];
            {
                ulonglong2 t0 = *(const ulonglong2*)&As2[cur][kk][ty * TM];
                ulonglong2 t1 = *(const ulonglong2*)&As2[cur][kk][ty * TM + 2];
                a2[0] = t0.x; a2[1] = t0.y; a2[2] = t1.x; a2[3] = t1.y;
            }
            ulonglong2 b0 = *(const ulonglong2*)&Bs[cur][kk][tx * 4];
            ulonglong2 b1 = *(const ulonglong2*)&Bs[cur][kk][64 + tx * 4];
#pragma unroll
            for (int u = 0; u < TM; u++) {
                ffma2(acc[u][0], a2[u], b0.x);
                ffma2(acc[u][1], a2[u], b0.y);
                ffma2(acc[u][2], a2[u], b1.x);
                ffma2(acc[u][3], a2[u], b1.y);
            }
        }
        __syncthreads();
        if ((c & 15) == 15) {
            int j0 = (c >> 4) * 128;
            // ascending j per thread: s (strip), then pair p, then lane — strict < keeps first
#pragma unroll
            for (int s = 0; s < 2; s++)
#pragma unroll
                for (int p = 0; p < 2; p++) {
                    int jb = j0 + s * 64 + tx * 4 + p * 2;
                    float bj0 = __ldg(bn + jb);
                    float bj1 = __ldg(bn + jb + 1);
#pragma unroll
                    for (int u = 0; u < TM; u++) {
                        ull A = acc[u][s * 2 + p];
                        float d0 = bj0 - 2.f * lo32(A);
                        if (d0 < bestv[u]) { bestv[u] = d0; besti[u] = jb; }
                        float d1 = bj1 - 2.f * hi32(A);
                        if (d1 < bestv[u]) { bestv[u] = d1; besti[u] = jb + 1; }
                        acc[u][s * 2 + p] = 0ull;
                    }
                }
        }
    }
    // cross-tx reduction via smem (alias tile buffers; all FMA/epilogue done)
    float* rv = (float*)&As2[0][0][0];          // 16 x 128 floats
    int* ri = (int*)rv + 2048;
#pragma unroll
    for (int u = 0; u < TM; u++) {
        rv[tx * 128 + ty * TM + u] = bestv[u];
        ri[tx * 128 + ty * TM + u] = besti[u];
    }
    __syncthreads();
    if (tid < 128) {
        float bvx = rv[tid];
        int bi = ri[tid];
#pragma unroll
        for (int t = 1; t < 16; t++) {
            float v = rv[t * 128 + tid];
            int ii = ri[t * 128 + tid];
            if (v < bvx || (v == bvx && ii < bi)) { bvx = v; bi = ii; }
        }
        idxout[(long)b * NPIX + i0 + tid] = bi;
    }
}

// ---------------- gather ----------------
__global__ void gather_kernel(const float* __restrict__ f2, const int* __restrict__ idx,
                              float* __restrict__ out) {
    long t = (long)blockIdx.x * blockDim.x + threadIdx.x;
    if (t >= (long)NB * C3 * NPIX) return;
    int j = (int)(t & (NPIX - 1));
    int c = (int)((t >> 12) & 255);
    int b = (int)(t >> 20);
    int id = idx[(long)b * NPIX + j];
    out[((long)b * 512 + 256 + c) * NPIX + j] = f2[((long)b * C3 + c) * NPIX + id];
}

// ---------------- launch ----------------
extern "C" void kernel_launch(void* const* d_in, const int* in_sizes, int n_in,
                              void* d_out, int out_size) {
    const float* x1 = (const float*)d_in[0];
    const float* x2 = (const float*)d_in[1];
    const float* w1 = (const float*)d_in[2];
    const float* b1 = (const float*)d_in[3];
    const float* w2 = (const float*)d_in[4];
    const float* b2 = (const float*)d_in[5];
    const float* w3 = (const float*)d_in[6];
    const float* b3 = (const float*)d_in[7];
    float* out = (float*)d_out;

    float *T1, *T2, *F2, *B2N, *Wt2, *Wt3;
    int* IDX;
    cudaGetSymbolAddress((void**)&T1, g_T1);
    cudaGetSymbolAddress((void**)&T2, g_T2);
    cudaGetSymbolAddress((void**)&F2, g_F2);
    cudaGetSymbolAddress((void**)&B2N, g_B2N);
    cudaGetSymbolAddress((void**)&IDX, g_IDX);
    cudaGetSymbolAddress((void**)&Wt2, g_Wt2);
    cudaGetSymbolAddress((void**)&Wt3, g_Wt3);

    prep_kernel<<<(C2 * 288 + C3 * 576 + 255) / 256, 256>>>(w2, w3, Wt2, Wt3);
    conv1_kernel<<<dim3(NPIX / 256, 8), 256>>>(x1, x2, w1, b1, T1);
    conv_gemm_kernel<64, 2><<<dim3(NPIX / 128, 1, 8), 512>>>(
        T1, C1, Wt2, 288, C2, b2, T2, (long)C2 * NPIX, T2 + (long)NB * C2 * NPIX,
        (long)C2 * NPIX);
    conv_gemm_kernel<128, 4><<<dim3(NPIX / 128, 2, 8), 512>>>(
        T2, C2, Wt3, 576, C3, b3, out, (long)512 * NPIX, F2, (long)C3 * NPIX);
    rownorm_kernel<<<dim3(NPIX / 256, NB), 256>>>(F2, B2N);
    dist_argmin_kernel<<<dim3(NPIX / 128, NB), 512>>>(out, F2, B2N, IDX);
    gather_kernel<<<(int)(((long)NB * C3 * NPIX + 255) / 256), 256>>>(F2, IDX, out);
}

// round 6
// speedup vs baseline: 2.2475x; 1.1724x over previous
#include <cuda_runtime.h>
#include <cstdint>

#define HH 64
#define WW 64
#define NPIX 4096
#define NB 4
#define C1 32
#define C2 64
#define C3 256

typedef unsigned long long ull;

__device__ __forceinline__ ull dup2(float v) {
    ull r;
    asm("mov.b64 %0, {%1, %1};" : "=l"(r) : "r"(__float_as_uint(v)));
    return r;
}
__device__ __forceinline__ void ffma2(ull& acc, ull a, ull b) {
    asm("fma.rn.f32x2 %0, %1, %2, %0;" : "+l"(acc) : "l"(a), "l"(b));
}
__device__ __forceinline__ float lo32(ull x) { return __uint_as_float((unsigned int)x); }
__device__ __forceinline__ float hi32(ull x) { return __uint_as_float((unsigned int)(x >> 32)); }

// ---------------- static device scratch ----------------
__device__ float g_T1[2 * NB * C1 * NPIX];
__device__ float g_T2[2 * NB * C2 * NPIX];
__device__ float g_F2[NB * C3 * NPIX];
__device__ float g_B2N[NB * NPIX];
__device__ int g_IDX[NB * NPIX];
__device__ float g_Wt2[288 * C2];
__device__ float g_Wt3[576 * C3];
__device__ float g_PVAL[4 * NB * NPIX];
__device__ int g_PIDX[4 * NB * NPIX];

// ---------------- prep: weight transposes ----------------
__global__ void prep_kernel(const float* __restrict__ w2, const float* __restrict__ w3,
                            float* __restrict__ Wt2, float* __restrict__ Wt3) {
    int t = blockIdx.x * blockDim.x + threadIdx.x;
    if (t < C2 * 288) {
        int co = t / 288, k = t - co * 288;
        Wt2[k * C2 + co] = w2[t];
    } else {
        int u = t - C2 * 288;
        if (u < C3 * 576) {
            int co = u / 576, k = u - co * 576;
            Wt3[k * C3 + co] = w3[u];
        }
    }
}

// ---------------- conv1 ----------------
__global__ void conv1_kernel(const float* __restrict__ x1, const float* __restrict__ x2,
                             const float* __restrict__ w, const float* __restrict__ bias,
                             float* __restrict__ out) {
    int p = blockIdx.x * blockDim.x + threadIdx.x;
    int z = blockIdx.y;
    if (p >= NPIX) return;
    const float* x = (z >> 2) ? x2 : x1;
    int b = z & 3;
    int y = p >> 6, xx = p & 63;
    const float* xb = x + (long)b * NPIX;
    float in[9];
#pragma unroll
    for (int ky = 0; ky < 3; ky++)
#pragma unroll
        for (int kx = 0; kx < 3; kx++) {
            int yy = y + ky - 1, xc = xx + kx - 1;
            in[ky * 3 + kx] =
                ((unsigned)yy < (unsigned)HH && (unsigned)xc < (unsigned)WW) ? xb[yy * WW + xc] : 0.f;
        }
#pragma unroll 4
    for (int co = 0; co < C1; co++) {
        float acc = bias[co];
#pragma unroll
        for (int t = 0; t < 9; t++) acc += w[co * 9 + t] * in[t];
        out[((long)z * C1 + co) * NPIX + p] = acc;
    }
}

// ---------------- implicit-GEMM conv: 256 thr, 2 CTA/SM, M-paired FFMA2 ----------------
// BM rows of output channels, BN=128 pixels, BK=16. MP = m-pairs per thread.
template <int BM, int MP>
__global__ void __launch_bounds__(256, 2)
conv_gemm_kernel(const float* __restrict__ in, int CI, const float* __restrict__ wT,
                 int Ktot, int CO, const float* __restrict__ bias,
                 float* __restrict__ outA, long strideA, float* __restrict__ outB, long strideB) {
    __shared__ __align__(16) float As[2][16][BM];   // plain weights
    __shared__ __align__(16) ull Bsd[2][16][128];   // duplicated pixels
    int z = blockIdx.z;
    int sel = z >> 2, bb = z & 3;
    float* out = sel ? outB : outA;
    long os = sel ? strideB : strideA;
    int m0 = blockIdx.y * BM;
    int n0 = blockIdx.x * 128;
    int tid = threadIdx.x;
    int tx = tid & 15, ty = tid >> 4;
    long inBase = (long)z * CI * NPIX;
    const int NA4 = BM / 64;  // float4 A loads per thread

    ull acc[MP][8];
#pragma unroll
    for (int u = 0; u < MP; u++)
#pragma unroll
        for (int v = 0; v < 8; v++) acc[u][v] = 0ull;

    float4 av[NA4];
    float2 bvp[4];
    int nch = Ktot / 16;

    auto ldA = [&](int c) {
        int k0 = c * 16;
#pragma unroll
        for (int i = 0; i < NA4; i++) {
            int e = tid + i * 256;
            int k = e / (BM / 4), p = e % (BM / 4);
            av[i] = *(const float4*)&wT[(long)(k0 + k) * CO + m0 + p * 4];
        }
    };
    auto ldB = [&](int c) {
        int k0 = c * 16;
#pragma unroll
        for (int i = 0; i < 4; i++) {
            int e2 = tid + i * 256;
            int k = e2 >> 6, np = e2 & 63;
            int gk = k0 + k;
            int ci = gk / 9, tap = gk - ci * 9;
            int kyy = tap / 3 - 1, kxx = tap - (tap / 3) * 3 - 1;
            long cb = inBase + (long)ci * NPIX;
            int gp0 = n0 + np * 2;
            int y0 = (gp0 >> 6) + kyy, x0 = (gp0 & 63) + kxx;
            float v0 = ((unsigned)y0 < (unsigned)HH && (unsigned)x0 < (unsigned)WW)
                           ? in[cb + (y0 << 6) + x0] : 0.f;
            int gp1 = gp0 + 1;
            int y1 = (gp1 >> 6) + kyy, x1 = (gp1 & 63) + kxx;
            float v1 = ((unsigned)y1 < (unsigned)HH && (unsigned)x1 < (unsigned)WW)
                           ? in[cb + (y1 << 6) + x1] : 0.f;
            bvp[i] = make_float2(v0, v1);
        }
    };
    auto stc = [&](int buf) {
#pragma unroll
        for (int i = 0; i < NA4; i++) {
            int e = tid + i * 256;
            int k = e / (BM / 4), p = e % (BM / 4);
            *(float4*)&As[buf][k][p * 4] = av[i];
        }
#pragma unroll
        for (int i = 0; i < 4; i++) {
            int e2 = tid + i * 256;
            int k = e2 >> 6, np = e2 & 63;
            ulonglong2 t;
            t.x = dup2(bvp[i].x);
            t.y = dup2(bvp[i].y);
            *(ulonglong2*)&Bsd[buf][k][np * 2] = t;
        }
    };

    ldA(0); ldB(0);
    stc(0);
    if (nch > 1) { ldA(1); ldB(1); }
    __syncthreads();

    for (int c = 0; c < nch; c++) {
        int cur = c & 1;
        if (c + 1 < nch) {
            stc(1 - cur);
            if (c + 2 < nch) { ldA(c + 2); ldB(c + 2); }
        }
#pragma unroll
        for (int kk = 0; kk < 16; kk++) {
            ull Ap[MP];
#pragma unroll
            for (int h = 0; h < MP / 2; h++) {
                ulonglong2 t = *(const ulonglong2*)&As[cur][kk][ty * 2 * MP + h * 4];
                Ap[h * 2] = t.x;
                Ap[h * 2 + 1] = t.y;
            }
#pragma unroll
            for (int s = 0; s < 4; s++) {
                ulonglong2 bq = *(const ulonglong2*)&Bsd[cur][kk][s * 32 + tx * 2];
#pragma unroll
                for (int mp = 0; mp < MP; mp++) {
                    ffma2(acc[mp][s * 2], Ap[mp], bq.x);
                    ffma2(acc[mp][s * 2 + 1], Ap[mp], bq.y);
                }
            }
        }
        __syncthreads();
    }
#pragma unroll
    for (int mp = 0; mp < MP; mp++) {
        int m = m0 + ty * 2 * MP + mp * 2;
        float b0 = bias[m], b1 = bias[m + 1];
        long base0 = (long)bb * os + (long)m * NPIX + n0;
        long base1 = base0 + NPIX;
#pragma unroll
        for (int s = 0; s < 4; s++) {
            float2 e0, e1;
            e0.x = lo32(acc[mp][s * 2]) + b0;
            e0.y = lo32(acc[mp][s * 2 + 1]) + b0;
            e1.x = hi32(acc[mp][s * 2]) + b1;
            e1.y = hi32(acc[mp][s * 2 + 1]) + b1;
            *(float2*)&out[base0 + s * 32 + tx * 2] = e0;
            *(float2*)&out[base1 + s * 32 + tx * 2] = e1;
        }
    }
}

// ---------------- key row norms ----------------
__global__ void rownorm_kernel(const float* __restrict__ f2, float* __restrict__ b2n) {
    int j = blockIdx.x * blockDim.x + threadIdx.x;
    int b = blockIdx.y;
    if (j >= NPIX) return;
    const float* p = f2 + (long)b * C3 * NPIX + j;
    float s = 0.f;
#pragma unroll 8
    for (int c = 0; c < C3; c++) {
        float v = p[(long)c * NPIX];
        s += v * v;
    }
    b2n[(long)b * NPIX + j] = s;
}

// ---------------- dist GEMM + argmin: 256 thr, 2 CTA/SM, j split 4 ways ----------------
__global__ void __launch_bounds__(256, 2)
dist_argmin_kernel(const float* __restrict__ f1out, const float* __restrict__ f2,
                   const float* __restrict__ b2n, float* __restrict__ pval,
                   int* __restrict__ pidx) {
    __shared__ __align__(16) float As[2][16][128];
    __shared__ __align__(16) ull Bsd[2][16][128];
    int b = blockIdx.z;
    int jq = blockIdx.y;
    int i0 = blockIdx.x * 128;
    const float* Q = f1out + (long)b * 512 * NPIX;
    const float* Kf = f2 + (long)b * 256 * NPIX;
    const float* bn = b2n + (long)b * NPIX;
    int tid = threadIdx.x;
    int tx = tid & 15, ty = tid >> 4;

    float bestv[8];
    int besti[8];
#pragma unroll
    for (int u = 0; u < 8; u++) { bestv[u] = 3.4e38f; besti[u] = 0; }

    ull acc[4][8];
#pragma unroll
    for (int u = 0; u < 4; u++)
#pragma unroll
        for (int v = 0; v < 8; v++) acc[u][v] = 0ull;

    float4 av[2];
    float2 bvp[4];
    auto ldA = [&](int c) {
        int k0 = (c & 15) * 16;
#pragma unroll
        for (int i = 0; i < 2; i++) {
            int e = tid + i * 256;
            int k = e >> 5, q = e & 31;
            av[i] = *(const float4*)&Q[(long)(k0 + k) * NPIX + i0 + q * 4];
        }
    };
    auto ldB = [&](int c) {
        int j0 = jq * 1024 + (c >> 4) * 128, k0 = (c & 15) * 16;
#pragma unroll
        for (int i = 0; i < 4; i++) {
            int e2 = tid + i * 256;
            int k = e2 >> 6, np = e2 & 63;
            bvp[i] = *(const float2*)&Kf[(long)(k0 + k) * NPIX + j0 + np * 2];
        }
    };
    auto stc = [&](int buf) {
#pragma unroll
        for (int i = 0; i < 2; i++) {
            int e = tid + i * 256;
            int k = e >> 5, q = e & 31;
            *(float4*)&As[buf][k][q * 4] = av[i];
        }
#pragma unroll
        for (int i = 0; i < 4; i++) {
            int e2 = tid + i * 256;
            int k = e2 >> 6, np = e2 & 63;
            ulonglong2 t;
            t.x = dup2(bvp[i].x);
            t.y = dup2(bvp[i].y);
            *(ulonglong2*)&Bsd[buf][k][np * 2] = t;
        }
    };

    const int NCH = 128;  // 8 j-tiles x 16 k-chunks
    ldA(0); ldB(0);
    stc(0);
    ldA(1); ldB(1);
    __syncthreads();

    for (int c = 0; c < NCH; c++) {
        int cur = c & 1;
        if (c + 1 < NCH) {
            stc(1 - cur);
            if (c + 2 < NCH) { ldA(c + 2); ldB(c + 2); }
        }
#pragma unroll
        for (int kk = 0; kk < 16; kk++) {
            ull Ap[4];
            {
                ulonglong2 t0 = *(const ulonglong2*)&As[cur][kk][ty * 8];
                ulonglong2 t1 = *(const ulonglong2*)&As[cur][kk][ty * 8 + 4];
                Ap[0] = t0.x; Ap[1] = t0.y; Ap[2] = t1.x; Ap[3] = t1.y;
            }
#pragma unroll
            for (int s = 0; s < 4; s++) {
                ulonglong2 bq = *(const ulonglong2*)&Bsd[cur][kk][s * 32 + tx * 2];
#pragma unroll
                for (int mp = 0; mp < 4; mp++) {
                    ffma2(acc[mp][s * 2], Ap[mp], bq.x);
                    ffma2(acc[mp][s * 2 + 1], Ap[mp], bq.y);
                }
            }
        }
        __syncthreads();
        if ((c & 15) == 15) {
            int j0 = jq * 1024 + (c >> 4) * 128;
            // ascending j per thread; strict < keeps smallest index on ties
#pragma unroll
            for (int s = 0; s < 4; s++)
#pragma unroll
                for (int p = 0; p < 2; p++) {
                    int jj = j0 + s * 32 + tx * 2 + p;
                    float bj = __ldg(&bn[jj]);
#pragma unroll
                    for (int mp = 0; mp < 4; mp++) {
                        ull A = acc[mp][s * 2 + p];
                        float d0 = bj - 2.f * lo32(A);
                        if (d0 < bestv[mp * 2]) { bestv[mp * 2] = d0; besti[mp * 2] = jj; }
                        float d1 = bj - 2.f * hi32(A);
                        if (d1 < bestv[mp * 2 + 1]) { bestv[mp * 2 + 1] = d1; besti[mp * 2 + 1] = jj; }
                        acc[mp][s * 2 + p] = 0ull;
                    }
                }
        }
    }
    // cross-tx reduction (alias tile smem; all MAC/LDS complete)
    float* rv = &As[0][0][0];               // 16 x 128 floats (8KB)
    int* ri = (int*)&As[1][0][0];           // 8KB
#pragma unroll
    for (int u = 0; u < 8; u++) {
        rv[tx * 128 + ty * 8 + u] = bestv[u];
        ri[tx * 128 + ty * 8 + u] = besti[u];
    }
    __syncthreads();
    if (tid < 128) {
        float bv = rv[tid];
        int bi = ri[tid];
#pragma unroll
        for (int t = 1; t < 16; t++) {
            float v = rv[t * 128 + tid];
            int ii = ri[t * 128 + tid];
            if (v < bv || (v == bv && ii < bi)) { bv = v; bi = ii; }
        }
        long o = ((long)jq * NB + b) * NPIX + i0 + tid;
        pval[o] = bv;
        pidx[o] = bi;
    }
}

// ---------------- merge 4 j-quarter candidates ----------------
__global__ void merge_kernel(const float* __restrict__ pval, const int* __restrict__ pidx,
                             int* __restrict__ idxout) {
    int t = blockIdx.x * blockDim.x + threadIdx.x;
    if (t >= NB * NPIX) return;
    int b = t >> 12, i = t & (NPIX - 1);
    float bv = pval[(long)b * NPIX + i];
    int bi = pidx[(long)b * NPIX + i];
#pragma unroll
    for (int jq = 1; jq < 4; jq++) {
        long o = ((long)jq * NB + b) * NPIX + i;
        float v = pval[o];
        int ii = pidx[o];
        if (v < bv || (v == bv && ii < bi)) { bv = v; bi = ii; }
    }
    idxout[t] = bi;
}

// ---------------- gather ----------------
__global__ void gather_kernel(const float* __restrict__ f2, const int* __restrict__ idx,
                              float* __restrict__ out) {
    long t = (long)blockIdx.x * blockDim.x + threadIdx.x;
    if (t >= (long)NB * C3 * NPIX) return;
    int j = (int)(t & (NPIX - 1));
    int c = (int)((t >> 12) & 255);
    int b = (int)(t >> 20);
    int id = idx[(long)b * NPIX + j];
    out[((long)b * 512 + 256 + c) * NPIX + j] = f2[((long)b * C3 + c) * NPIX + id];
}

// ---------------- launch ----------------
extern "C" void kernel_launch(void* const* d_in, const int* in_sizes, int n_in,
                              void* d_out, int out_size) {
    const float* x1 = (const float*)d_in[0];
    const float* x2 = (const float*)d_in[1];
    const float* w1 = (const float*)d_in[2];
    const float* b1 = (const float*)d_in[3];
    const float* w2 = (const float*)d_in[4];
    const float* b2 = (const float*)d_in[5];
    const float* w3 = (const float*)d_in[6];
    const float* b3 = (const float*)d_in[7];
    float* out = (float*)d_out;

    float *T1, *T2, *F2, *B2N, *Wt2, *Wt3, *PVAL;
    int *IDX, *PIDX;
    cudaGetSymbolAddress((void**)&T1, g_T1);
    cudaGetSymbolAddress((void**)&T2, g_T2);
    cudaGetSymbolAddress((void**)&F2, g_F2);
    cudaGetSymbolAddress((void**)&B2N, g_B2N);
    cudaGetSymbolAddress((void**)&IDX, g_IDX);
    cudaGetSymbolAddress((void**)&Wt2, g_Wt2);
    cudaGetSymbolAddress((void**)&Wt3, g_Wt3);
    cudaGetSymbolAddress((void**)&PVAL, g_PVAL);
    cudaGetSymbolAddress((void**)&PIDX, g_PIDX);

    prep_kernel<<<(C2 * 288 + C3 * 576 + 255) / 256, 256>>>(w2, w3, Wt2, Wt3);
    conv1_kernel<<<dim3(NPIX / 256, 8), 256>>>(x1, x2, w1, b1, T1);
    conv_gemm_kernel<64, 2><<<dim3(32, 1, 8), 256>>>(
        T1, C1, Wt2, 288, C2, b2, T2, (long)C2 * NPIX, T2 + (long)NB * C2 * NPIX,
        (long)C2 * NPIX);
    conv_gemm_kernel<128, 4><<<dim3(32, 2, 8), 256>>>(
        T2, C2, Wt3, 576, C3, b3, out, (long)512 * NPIX, F2, (long)C3 * NPIX);
    rownorm_kernel<<<dim3(NPIX / 256, NB), 256>>>(F2, B2N);
    dist_argmin_kernel<<<dim3(32, 4, NB), 256>>>(out, F2, B2N, PVAL, PIDX);
    merge_kernel<<<(NB * NPIX + 255) / 256, 256>>>(PVAL, PIDX, IDX);
    gather_kernel<<<(int)(((long)NB * C3 * NPIX + 255) / 256), 256>>>(F2, IDX, out);
}

// round 7
// speedup vs baseline: 2.2946x; 1.0210x over previous
#include <cuda_runtime.h>
#include <cstdint>

#define HH 64
#define WW 64
#define NPIX 4096
#define NB 4
#define C1 32
#define C2 64
#define C3 256

typedef unsigned long long ull;

__device__ __forceinline__ ull dup2(float v) {
    ull r;
    asm("mov.b64 %0, {%1, %1};" : "=l"(r) : "r"(__float_as_uint(v)));
    return r;
}
__device__ __forceinline__ void ffma2(ull& acc, ull a, ull b) {
    asm("fma.rn.f32x2 %0, %1, %2, %0;" : "+l"(acc) : "l"(a), "l"(b));
}
__device__ __forceinline__ float lo32(ull x) { return __uint_as_float((unsigned int)x); }
__device__ __forceinline__ float hi32(ull x) { return __uint_as_float((unsigned int)(x >> 32)); }
__device__ __forceinline__ uint32_t smem_u32(const void* p) {
    uint32_t a;
    asm("{ .reg .u64 t; cvta.to.shared.u64 t, %1; cvt.u32.u64 %0, t; }" : "=r"(a) : "l"(p));
    return a;
}
#define CP_ASYNC16(dst, src) \
    asm volatile("cp.async.cg.shared.global [%0], [%1], 16;" :: "r"(dst), "l"(src) : "memory")
#define CP_COMMIT() asm volatile("cp.async.commit_group;" ::: "memory")
#define CP_WAIT1() asm volatile("cp.async.wait_group 1;" ::: "memory")

// ---------------- static device scratch ----------------
__device__ float g_T1[2 * NB * C1 * NPIX];
__device__ float g_T2[2 * NB * C2 * NPIX];
__device__ float g_F2[NB * C3 * NPIX];
__device__ float g_B2N[NB * NPIX];
__device__ int g_IDX[NB * NPIX];
__device__ float g_Wt2[288 * C2];
__device__ float g_Wt3[576 * C3];
__device__ float g_PVAL[4 * NB * NPIX];
__device__ int g_PIDX[4 * NB * NPIX];
__device__ __align__(16) ull g_QD[(long)NB * C3 * NPIX];  // duplicated queries

// ---------------- prep: weight transposes ----------------
__global__ void prep_kernel(const float* __restrict__ w2, const float* __restrict__ w3,
                            float* __restrict__ Wt2, float* __restrict__ Wt3) {
    int t = blockIdx.x * blockDim.x + threadIdx.x;
    if (t < C2 * 288) {
        int co = t / 288, k = t - co * 288;
        Wt2[k * C2 + co] = w2[t];
    } else {
        int u = t - C2 * 288;
        if (u < C3 * 576) {
            int co = u / 576, k = u - co * 576;
            Wt3[k * C3 + co] = w3[u];
        }
    }
}

// ---------------- conv1 ----------------
__global__ void conv1_kernel(const float* __restrict__ x1, const float* __restrict__ x2,
                             const float* __restrict__ w, const float* __restrict__ bias,
                             float* __restrict__ out) {
    int p = blockIdx.x * blockDim.x + threadIdx.x;
    int z = blockIdx.y;
    if (p >= NPIX) return;
    const float* x = (z >> 2) ? x2 : x1;
    int b = z & 3;
    int y = p >> 6, xx = p & 63;
    const float* xb = x + (long)b * NPIX;
    float in[9];
#pragma unroll
    for (int ky = 0; ky < 3; ky++)
#pragma unroll
        for (int kx = 0; kx < 3; kx++) {
            int yy = y + ky - 1, xc = xx + kx - 1;
            in[ky * 3 + kx] =
                ((unsigned)yy < (unsigned)HH && (unsigned)xc < (unsigned)WW) ? xb[yy * WW + xc] : 0.f;
        }
#pragma unroll 4
    for (int co = 0; co < C1; co++) {
        float acc = bias[co];
#pragma unroll
        for (int t = 0; t < 9; t++) acc += w[co * 9 + t] * in[t];
        out[((long)z * C1 + co) * NPIX + p] = acc;
    }
}

// ---------------- implicit-GEMM conv (unchanged from round 6) ----------------
template <int BM, int MP>
__global__ void __launch_bounds__(256, 2)
conv_gemm_kernel(const float* __restrict__ in, int CI, const float* __restrict__ wT,
                 int Ktot, int CO, const float* __restrict__ bias,
                 float* __restrict__ outA, long strideA, float* __restrict__ outB, long strideB) {
    __shared__ __align__(16) float As[2][16][BM];
    __shared__ __align__(16) ull Bsd[2][16][128];
    int z = blockIdx.z;
    int sel = z >> 2, bb = z & 3;
    float* out = sel ? outB : outA;
    long os = sel ? strideB : strideA;
    int m0 = blockIdx.y * BM;
    int n0 = blockIdx.x * 128;
    int tid = threadIdx.x;
    int tx = tid & 15, ty = tid >> 4;
    long inBase = (long)z * CI * NPIX;
    const int NA4 = BM / 64;

    ull acc[MP][8];
#pragma unroll
    for (int u = 0; u < MP; u++)
#pragma unroll
        for (int v = 0; v < 8; v++) acc[u][v] = 0ull;

    float4 av[NA4];
    float2 bvp[4];
    int nch = Ktot / 16;

    auto ldA = [&](int c) {
        int k0 = c * 16;
#pragma unroll
        for (int i = 0; i < NA4; i++) {
            int e = tid + i * 256;
            int k = e / (BM / 4), p = e % (BM / 4);
            av[i] = *(const float4*)&wT[(long)(k0 + k) * CO + m0 + p * 4];
        }
    };
    auto ldB = [&](int c) {
        int k0 = c * 16;
#pragma unroll
        for (int i = 0; i < 4; i++) {
            int e2 = tid + i * 256;
            int k = e2 >> 6, np = e2 & 63;
            int gk = k0 + k;
            int ci = gk / 9, tap = gk - ci * 9;
            int kyy = tap / 3 - 1, kxx = tap - (tap / 3) * 3 - 1;
            long cb = inBase + (long)ci * NPIX;
            int gp0 = n0 + np * 2;
            int y0 = (gp0 >> 6) + kyy, x0 = (gp0 & 63) + kxx;
            float v0 = ((unsigned)y0 < (unsigned)HH && (unsigned)x0 < (unsigned)WW)
                           ? in[cb + (y0 << 6) + x0] : 0.f;
            int gp1 = gp0 + 1;
            int y1 = (gp1 >> 6) + kyy, x1 = (gp1 & 63) + kxx;
            float v1 = ((unsigned)y1 < (unsigned)HH && (unsigned)x1 < (unsigned)WW)
                           ? in[cb + (y1 << 6) + x1] : 0.f;
            bvp[i] = make_float2(v0, v1);
        }
    };
    auto stc = [&](int buf) {
#pragma unroll
        for (int i = 0; i < NA4; i++) {
            int e = tid + i * 256;
            int k = e / (BM / 4), p = e % (BM / 4);
            *(float4*)&As[buf][k][p * 4] = av[i];
        }
#pragma unroll
        for (int i = 0; i < 4; i++) {
            int e2 = tid + i * 256;
            int k = e2 >> 6, np = e2 & 63;
            ulonglong2 t;
            t.x = dup2(bvp[i].x);
            t.y = dup2(bvp[i].y);
            *(ulonglong2*)&Bsd[buf][k][np * 2] = t;
        }
    };

    ldA(0); ldB(0);
    stc(0);
    if (nch > 1) { ldA(1); ldB(1); }
    __syncthreads();

    for (int c = 0; c < nch; c++) {
        int cur = c & 1;
        if (c + 1 < nch) {
            stc(1 - cur);
            if (c + 2 < nch) { ldA(c + 2); ldB(c + 2); }
        }
#pragma unroll
        for (int kk = 0; kk < 16; kk++) {
            ull Ap[MP];
#pragma unroll
            for (int h = 0; h < MP / 2; h++) {
                ulonglong2 t = *(const ulonglong2*)&As[cur][kk][ty * 2 * MP + h * 4];
                Ap[h * 2] = t.x;
                Ap[h * 2 + 1] = t.y;
            }
#pragma unroll
            for (int s = 0; s < 4; s++) {
                ulonglong2 bq = *(const ulonglong2*)&Bsd[cur][kk][s * 32 + tx * 2];
#pragma unroll
                for (int mp = 0; mp < MP; mp++) {
                    ffma2(acc[mp][s * 2], Ap[mp], bq.x);
                    ffma2(acc[mp][s * 2 + 1], Ap[mp], bq.y);
                }
            }
        }
        __syncthreads();
    }
#pragma unroll
    for (int mp = 0; mp < MP; mp++) {
        int m = m0 + ty * 2 * MP + mp * 2;
        float b0 = bias[m], b1 = bias[m + 1];
        long base0 = (long)bb * os + (long)m * NPIX + n0;
        long base1 = base0 + NPIX;
#pragma unroll
        for (int s = 0; s < 4; s++) {
            float2 e0, e1;
            e0.x = lo32(acc[mp][s * 2]) + b0;
            e0.y = lo32(acc[mp][s * 2 + 1]) + b0;
            e1.x = hi32(acc[mp][s * 2]) + b1;
            e1.y = hi32(acc[mp][s * 2 + 1]) + b1;
            *(float2*)&out[base0 + s * 32 + tx * 2] = e0;
            *(float2*)&out[base1 + s * 32 + tx * 2] = e1;
        }
    }
}

// ---------------- fused: Q duplication + key row norms ----------------
__global__ void dupq_norm_kernel(const float* __restrict__ f1out, const float* __restrict__ f2,
                                 ull* __restrict__ QD, float* __restrict__ b2n) {
    int bx = blockIdx.x;
    int tid = threadIdx.x;
    if (bx < 8192) {
        long t2 = ((long)bx * 256 + tid) * 2;  // element pair index
        int b = (int)(t2 >> 20);
        int c = (int)((t2 >> 12) & 255);
        int i = (int)(t2 & 4095);
        float2 v = *(const float2*)&f1out[((long)b * 512 + c) * NPIX + i];
        ull* d = &QD[((long)b * C3 + c) * NPIX + i];
        d[0] = dup2(v.x);
        d[1] = dup2(v.y);
    } else {
        int t = (bx - 8192) * 256 + tid;  // NB*NPIX norms
        int b = t >> 12, j = t & 4095;
        const float* p = f2 + (long)b * C3 * NPIX + j;
        float s = 0.f;
#pragma unroll 8
        for (int c = 0; c < C3; c++) {
            float v = p[(long)c * NPIX];
            s += v * v;
        }
        b2n[t] = s;
    }
}

// ---------------- dist GEMM + argmin: cp.async 3-stage, N-paired FFMA2 ----------------
#define DSM_A(st) ((st) * 16384)
#define DSM_B(st) (49152 + (st) * 8192)
#define DSM_TOTAL 73728

__global__ void __launch_bounds__(256, 2)
dist_argmin_kernel(const ull* __restrict__ QD, const float* __restrict__ f2,
                   const float* __restrict__ b2n, float* __restrict__ pval,
                   int* __restrict__ pidx) {
    extern __shared__ __align__(16) char dsm[];
    uint32_t sbase = smem_u32(dsm);
    int b = blockIdx.z;
    int jq = blockIdx.y;
    int i0 = blockIdx.x * 128;
    const ull* Qd = QD + ((long)b * C3) * NPIX;
    const float* Kf = f2 + (long)b * C3 * NPIX;
    const float* bn = b2n + (long)b * NPIX;
    int tid = threadIdx.x;
    int tx = tid & 15, ty = tid >> 4;

    float bestv[8];
    int besti[8];
#pragma unroll
    for (int u = 0; u < 8; u++) { bestv[u] = 3.4e38f; besti[u] = 0; }

    ull acc[8][4];
#pragma unroll
    for (int u = 0; u < 8; u++)
#pragma unroll
        for (int v = 0; v < 4; v++) acc[u][v] = 0ull;

    // per-chunk async loads: A = 16 rows x 128 dup'd ull (16KB), B = 16 x 128 f32 (8KB)
    auto issue = [&](int c, int st) {
        int k0 = (c & 15) * 16;
        int j0 = jq * 1024 + (c >> 4) * 128;
        uint32_t da = sbase + DSM_A(st);
        uint32_t db = sbase + DSM_B(st);
#pragma unroll
        for (int it = 0; it < 4; it++) {
            int e = tid + it * 256;        // 1024 16B-chunks
            int row = e >> 6, c16 = e & 63;
            const ull* src = Qd + (long)(k0 + row) * NPIX + i0 + c16 * 2;
            CP_ASYNC16(da + (uint32_t)(row * 1024 + c16 * 16), src);
        }
#pragma unroll
        for (int it = 0; it < 2; it++) {
            int e = tid + it * 256;        // 512 16B-chunks
            int row = e >> 5, c16 = e & 31;
            const float* src = Kf + (long)(k0 + row) * NPIX + j0 + c16 * 4;
            CP_ASYNC16(db + (uint32_t)(row * 512 + c16 * 16), src);
        }
        CP_COMMIT();
    };

    const int NCH = 128;  // 8 j-tiles x 16 k-chunks
    issue(0, 0);
    issue(1, 1);

    for (int c = 0; c < NCH; c++) {
        int st = c % 3;
        CP_WAIT1();
        __syncthreads();
        if (c + 2 < NCH) issue(c + 2, (c + 2) % 3);
        const ull* AD = (const ull*)(dsm + DSM_A(st));
        const float* Bs = (const float*)(dsm + DSM_B(st));
#pragma unroll
        for (int kk = 0; kk < 16; kk++) {
            ull a2[8];
#pragma unroll
            for (int h = 0; h < 4; h++) {
                ulonglong2 t = *(const ulonglong2*)&AD[kk * 128 + ty * 8 + h * 2];
                a2[h * 2] = t.x;
                a2[h * 2 + 1] = t.y;
            }
            ulonglong2 bp0 = *(const ulonglong2*)&Bs[kk * 128 + tx * 8];
            ulonglong2 bp1 = *(const ulonglong2*)&Bs[kk * 128 + tx * 8 + 4];
#pragma unroll
            for (int u = 0; u < 8; u++) {
                ffma2(acc[u][0], a2[u], bp0.x);
                ffma2(acc[u][1], a2[u], bp0.y);
                ffma2(acc[u][2], a2[u], bp1.x);
                ffma2(acc[u][3], a2[u], bp1.y);
            }
        }
        if ((c & 15) == 15) {
            int j0 = jq * 1024 + (c >> 4) * 128;
            // per-thread j ascending (np, then pair lane); strict < keeps first index
#pragma unroll
            for (int np = 0; np < 4; np++) {
                int jj = j0 + tx * 8 + np * 2;
                float bj0 = __ldg(&bn[jj]);
                float bj1 = __ldg(&bn[jj + 1]);
#pragma unroll
                for (int u = 0; u < 8; u++) {
                    ull A = acc[u][np];
                    float d0 = bj0 - 2.f * lo32(A);
                    if (d0 < bestv[u]) { bestv[u] = d0; besti[u] = jj; }
                    float d1 = bj1 - 2.f * hi32(A);
                    if (d1 < bestv[u]) { bestv[u] = d1; besti[u] = jj + 1; }
                    acc[u][np] = 0ull;
                }
            }
        }
    }
    // cross-tx reduction (alias stage smem; all tile reads complete)
    __syncthreads();
    float* rv = (float*)dsm;               // 16 x 128 floats
    int* ri = (int*)(dsm + 8192);
#pragma unroll
    for (int u = 0; u < 8; u++) {
        rv[tx * 128 + ty * 8 + u] = bestv[u];
        ri[tx * 128 + ty * 8 + u] = besti[u];
    }
    __syncthreads();
    if (tid < 128) {
        float bv = rv[tid];
        int bi = ri[tid];
#pragma unroll
        for (int t = 1; t < 16; t++) {
            float v = rv[t * 128 + tid];
            int ii = ri[t * 128 + tid];
            if (v < bv || (v == bv && ii < bi)) { bv = v; bi = ii; }
        }
        long o = ((long)jq * NB + b) * NPIX + i0 + tid;
        pval[o] = bv;
        pidx[o] = bi;
    }
}

// ---------------- merge 4 j-quarter candidates ----------------
__global__ void merge_kernel(const float* __restrict__ pval, const int* __restrict__ pidx,
                             int* __restrict__ idxout) {
    int t = blockIdx.x * blockDim.x + threadIdx.x;
    if (t >= NB * NPIX) return;
    int b = t >> 12, i = t & (NPIX - 1);
    float bv = pval[(long)b * NPIX + i];
    int bi = pidx[(long)b * NPIX + i];
#pragma unroll
    for (int jq = 1; jq < 4; jq++) {
        long o = ((long)jq * NB + b) * NPIX + i;
        float v = pval[o];
        int ii = pidx[o];
        if (v < bv || (v == bv && ii < bi)) { bv = v; bi = ii; }
    }
    idxout[t] = bi;
}

// ---------------- gather ----------------
__global__ void gather_kernel(const float* __restrict__ f2, const int* __restrict__ idx,
                              float* __restrict__ out) {
    long t = (long)blockIdx.x * blockDim.x + threadIdx.x;
    if (t >= (long)NB * C3 * NPIX) return;
    int j = (int)(t & (NPIX - 1));
    int c = (int)((t >> 12) & 255);
    int b = (int)(t >> 20);
    int id = idx[(long)b * NPIX + j];
    out[((long)b * 512 + 256 + c) * NPIX + j] = f2[((long)b * C3 + c) * NPIX + id];
}

// ---------------- launch ----------------
extern "C" void kernel_launch(void* const* d_in, const int* in_sizes, int n_in,
                              void* d_out, int out_size) {
    const float* x1 = (const float*)d_in[0];
    const float* x2 = (const float*)d_in[1];
    const float* w1 = (const float*)d_in[2];
    const float* b1 = (const float*)d_in[3];
    const float* w2 = (const float*)d_in[4];
    const float* b2 = (const float*)d_in[5];
    const float* w3 = (const float*)d_in[6];
    const float* b3 = (const float*)d_in[7];
    float* out = (float*)d_out;

    float *T1, *T2, *F2, *B2N, *Wt2, *Wt3, *PVAL;
    int *IDX, *PIDX;
    ull* QD;
    cudaGetSymbolAddress((void**)&T1, g_T1);
    cudaGetSymbolAddress((void**)&T2, g_T2);
    cudaGetSymbolAddress((void**)&F2, g_F2);
    cudaGetSymbolAddress((void**)&B2N, g_B2N);
    cudaGetSymbolAddress((void**)&IDX, g_IDX);
    cudaGetSymbolAddress((void**)&Wt2, g_Wt2);
    cudaGetSymbolAddress((void**)&Wt3, g_Wt3);
    cudaGetSymbolAddress((void**)&PVAL, g_PVAL);
    cudaGetSymbolAddress((void**)&PIDX, g_PIDX);
    cudaGetSymbolAddress((void**)&QD, g_QD);

    cudaFuncSetAttribute(dist_argmin_kernel, cudaFuncAttributeMaxDynamicSharedMemorySize,
                         DSM_TOTAL);

    prep_kernel<<<(C2 * 288 + C3 * 576 + 255) / 256, 256>>>(w2, w3, Wt2, Wt3);
    conv1_kernel<<<dim3(NPIX / 256, 8), 256>>>(x1, x2, w1, b1, T1);
    conv_gemm_kernel<64, 2><<<dim3(32, 1, 8), 256>>>(
        T1, C1, Wt2, 288, C2, b2, T2, (long)C2 * NPIX, T2 + (long)NB * C2 * NPIX,
        (long)C2 * NPIX);
    conv_gemm_kernel<128, 4><<<dim3(32, 2, 8), 256>>>(
        T2, C2, Wt3, 576, C3, b3, out, (long)512 * NPIX, F2, (long)C3 * NPIX);
    dupq_norm_kernel<<<8192 + 64, 256>>>(out, F2, QD, B2N);
    dist_argmin_kernel<<<dim3(32, 4, NB), 256, DSM_TOTAL>>>(QD, F2, B2N, PVAL, PIDX);
    merge_kernel<<<(NB * NPIX + 255) / 256, 256>>>(PVAL, PIDX, IDX);
    gather_kernel<<<(int)(((long)NB * C3 * NPIX + 255) / 256), 256>>>(F2, IDX, out);
}